// round 3
// baseline (speedup 1.0000x reference)
#include <cuda_runtime.h>
#include <cstdint>

// Problem constants
#define BB 4
#define SS 2048
#define HH 2048
#define NH 16
#define HD 128
#define MM (BB*SS)            // 8192 rows

// Scratch (allocation-free: __device__ globals)
__device__ float g_q[BB*NH*SS*HD];   // [b,h,s,d]
__device__ float g_k[BB*NH*SS*HD];
__device__ float g_v[BB*NH*SS*HD];
__device__ float g_o[MM*HH];         // [b,s,h*d]

__device__ __forceinline__ uint32_t f2tf(float f) {
    uint32_t u; asm("cvt.rna.tf32.f32 %0, %1;" : "=r"(u) : "f"(f)); return u;
}

__device__ __forceinline__ void mma_m16n8k8(float c[4], const uint32_t a[4], const uint32_t b[2]) {
    asm volatile(
        "mma.sync.aligned.m16n8k8.row.col.f32.tf32.tf32.f32 "
        "{%0,%1,%2,%3},{%4,%5,%6,%7},{%8,%9},{%0,%1,%2,%3};"
        : "+f"(c[0]), "+f"(c[1]), "+f"(c[2]), "+f"(c[3])
        : "r"(a[0]), "r"(a[1]), "r"(a[2]), "r"(a[3]), "r"(b[0]), "r"(b[1]));
}

// ============================================================================
// GEMM: C[M,N] = A[M,K] * Bw[N,K]^T   (tf32 mma, 128x128x16 tiles, 256 thr)
// qkv_mode=1: scatter C[m][n] -> out[b,h,s,d] layout (m=b*S+s, n=h*HD+d)
// ============================================================================
__global__ void __launch_bounds__(256) gemm_tf32_kernel(
    const float* __restrict__ A, const float* __restrict__ Bw,
    float* __restrict__ C, int qkv_mode)
{
    const int K = HH, N = HH;
    __shared__ uint32_t As[2][128][20];   // stride 20 -> conflict-free frag loads
    __shared__ uint32_t Bs[2][128][20];

    const int tid  = threadIdx.x;
    const int lane = tid & 31;
    const int warp = tid >> 5;
    const int g = lane >> 2, t = lane & 3;
    const int wm = warp & 3, wn = warp >> 2;     // 4 x 2 warp grid, warp tile 32x64
    const int rowBase = blockIdx.y * 128;
    const int colBase = blockIdx.x * 128;

    const int lr  = tid >> 2;   // 0..63
    const int lc4 = tid & 3;    // float4 column within the 16-wide k-tile

    const float4* Ag0 = reinterpret_cast<const float4*>(A  + (size_t)(rowBase + lr)      * K) + lc4;
    const float4* Ag1 = reinterpret_cast<const float4*>(A  + (size_t)(rowBase + lr + 64) * K) + lc4;
    const float4* Bg0 = reinterpret_cast<const float4*>(Bw + (size_t)(colBase + lr)      * K) + lc4;
    const float4* Bg1 = reinterpret_cast<const float4*>(Bw + (size_t)(colBase + lr + 64) * K) + lc4;

    float acc[2][8][4];
    #pragma unroll
    for (int mi = 0; mi < 2; mi++)
        #pragma unroll
        for (int ni = 0; ni < 8; ni++)
            #pragma unroll
            for (int j = 0; j < 4; j++) acc[mi][ni][j] = 0.f;

    float4 fa0, fa1, fb0, fb1;

    // prologue: tile 0
    fa0 = Ag0[0]; fa1 = Ag1[0]; fb0 = Bg0[0]; fb1 = Bg1[0];
    {
        uint4 u;
        u.x=f2tf(fa0.x); u.y=f2tf(fa0.y); u.z=f2tf(fa0.z); u.w=f2tf(fa0.w);
        *reinterpret_cast<uint4*>(&As[0][lr][lc4*4]) = u;
        u.x=f2tf(fa1.x); u.y=f2tf(fa1.y); u.z=f2tf(fa1.z); u.w=f2tf(fa1.w);
        *reinterpret_cast<uint4*>(&As[0][lr+64][lc4*4]) = u;
        u.x=f2tf(fb0.x); u.y=f2tf(fb0.y); u.z=f2tf(fb0.z); u.w=f2tf(fb0.w);
        *reinterpret_cast<uint4*>(&Bs[0][lr][lc4*4]) = u;
        u.x=f2tf(fb1.x); u.y=f2tf(fb1.y); u.z=f2tf(fb1.z); u.w=f2tf(fb1.w);
        *reinterpret_cast<uint4*>(&Bs[0][lr+64][lc4*4]) = u;
    }
    __syncthreads();

    const int nk = K / 16;   // 128
    #pragma unroll 1
    for (int kt = 0; kt < nk; kt++) {
        const int cur = kt & 1, nxt = cur ^ 1;
        const bool has = (kt + 1 < nk);
        if (has) {
            int i = (kt + 1) * 4;
            fa0 = Ag0[i]; fa1 = Ag1[i]; fb0 = Bg0[i]; fb1 = Bg1[i];
        }
        #pragma unroll
        for (int kk = 0; kk < 2; kk++) {
            uint32_t a[2][4];
            #pragma unroll
            for (int mi = 0; mi < 2; mi++) {
                int r = wm*32 + mi*16 + g;
                a[mi][0] = As[cur][r  ][kk*8 + t];
                a[mi][1] = As[cur][r+8][kk*8 + t];
                a[mi][2] = As[cur][r  ][kk*8 + t + 4];
                a[mi][3] = As[cur][r+8][kk*8 + t + 4];
            }
            #pragma unroll
            for (int ni = 0; ni < 8; ni++) {
                uint32_t bf[2];
                int bn = wn*64 + ni*8 + g;
                bf[0] = Bs[cur][bn][kk*8 + t];
                bf[1] = Bs[cur][bn][kk*8 + t + 4];
                mma_m16n8k8(acc[0][ni], a[0], bf);
                mma_m16n8k8(acc[1][ni], a[1], bf);
            }
        }
        if (has) {
            uint4 u;
            u.x=f2tf(fa0.x); u.y=f2tf(fa0.y); u.z=f2tf(fa0.z); u.w=f2tf(fa0.w);
            *reinterpret_cast<uint4*>(&As[nxt][lr][lc4*4]) = u;
            u.x=f2tf(fa1.x); u.y=f2tf(fa1.y); u.z=f2tf(fa1.z); u.w=f2tf(fa1.w);
            *reinterpret_cast<uint4*>(&As[nxt][lr+64][lc4*4]) = u;
            u.x=f2tf(fb0.x); u.y=f2tf(fb0.y); u.z=f2tf(fb0.z); u.w=f2tf(fb0.w);
            *reinterpret_cast<uint4*>(&Bs[nxt][lr][lc4*4]) = u;
            u.x=f2tf(fb1.x); u.y=f2tf(fb1.y); u.z=f2tf(fb1.z); u.w=f2tf(fb1.w);
            *reinterpret_cast<uint4*>(&Bs[nxt][lr+64][lc4*4]) = u;
        }
        __syncthreads();
    }

    // epilogue
    #pragma unroll
    for (int mi = 0; mi < 2; mi++) {
        int r0 = rowBase + wm*32 + mi*16 + g;
        #pragma unroll
        for (int ni = 0; ni < 8; ni++) {
            int cc = colBase + wn*64 + ni*8 + 2*t;
            if (!qkv_mode) {
                float* dst = C + (size_t)r0 * N + cc;
                *reinterpret_cast<float2*>(dst)          = make_float2(acc[mi][ni][0], acc[mi][ni][1]);
                *reinterpret_cast<float2*>(dst + 8ull*N) = make_float2(acc[mi][ni][2], acc[mi][ni][3]);
            } else {
                int bb2 = r0 >> 11;         // /2048
                int ss2 = r0 & 2047;
                int hh2 = cc >> 7;          // /128
                int dd  = cc & 127;
                float* dst = C + (((size_t)(bb2*NH + hh2)) << 18) + (size_t)ss2*HD + dd;
                *reinterpret_cast<float2*>(dst)          = make_float2(acc[mi][ni][0], acc[mi][ni][1]);
                *reinterpret_cast<float2*>(dst + 8*HD)   = make_float2(acc[mi][ni][2], acc[mi][ni][3]);
            }
        }
    }
}

// ============================================================================
// Flash attention (causal), tf32 mma. Q tile 128, K/V tile 64, 256 threads.
// Grid: (S/128, NH, B). Each warp owns 16 q-rows.
// ============================================================================
#define QS_STRIDE 132   //  4 mod 32 -> conflict-free A/B frag loads
#define KS_STRIDE 132
#define VS_STRIDE 136   //  8 mod 32 -> conflict-free V B-frag loads
#define PS_STRIDE 68    //  4 mod 32

#define ATTN_SMEM ((128*QS_STRIDE + 64*KS_STRIDE + 64*VS_STRIDE + 128*PS_STRIDE) * 4)

__global__ void __launch_bounds__(256) attn_kernel()
{
    extern __shared__ uint32_t sm[];
    uint32_t* Qs = sm;
    uint32_t* Ks = Qs + 128*QS_STRIDE;
    uint32_t* Vs = Ks + 64*KS_STRIDE;
    uint32_t* Ps = Vs + 64*VS_STRIDE;

    const int tid  = threadIdx.x;
    const int lane = tid & 31;
    const int warp = tid >> 5;
    const int g = lane >> 2, t = lane & 3;

    const int qt = blockIdx.x;
    const int h  = blockIdx.y;
    const int b  = blockIdx.z;

    const size_t base = ((size_t)(b*NH + h)) << 18;   // * S*HD
    const float* Qg = g_q + base + (size_t)qt * 128 * HD;
    const float* Kg = g_k + base;
    const float* Vg = g_v + base;

    // load Q tile (128x128) -> tf32 smem
    #pragma unroll
    for (int i = 0; i < 16; i++) {
        int idx = i*256 + tid;          // float4 index
        int r = idx >> 5, c4 = idx & 31;
        float4 f = reinterpret_cast<const float4*>(Qg)[idx];
        uint32_t* d = &Qs[r*QS_STRIDE + c4*4];
        d[0]=f2tf(f.x); d[1]=f2tf(f.y); d[2]=f2tf(f.z); d[3]=f2tf(f.w);
    }

    float o[16][4];
    #pragma unroll
    for (int ni = 0; ni < 16; ni++)
        #pragma unroll
        for (int j = 0; j < 4; j++) o[ni][j] = 0.f;

    const float NEGINF = -1e30f;
    float mrow0 = NEGINF, mrow1 = NEGINF;
    float lrow0 = 0.f,    lrow1 = 0.f;
    const float sl = 0.088388347648318447f * 1.4426950408889634f;  // 1/sqrt(128)*log2(e)

    const int qrow = warp*16 + g;       // local rows qrow, qrow+8
    const int nkt = 2*qt + 2;           // causal K-tile count

    #pragma unroll 1
    for (int kt = 0; kt < nkt; kt++) {
        // load K, V tiles (64x128 each)
        const float4* Kg4 = reinterpret_cast<const float4*>(Kg + (size_t)kt*64*HD);
        const float4* Vg4 = reinterpret_cast<const float4*>(Vg + (size_t)kt*64*HD);
        #pragma unroll
        for (int i = 0; i < 8; i++) {
            int idx = i*256 + tid;
            int r = idx >> 5, c4 = idx & 31;
            float4 f = Kg4[idx];
            uint32_t* d = &Ks[r*KS_STRIDE + c4*4];
            d[0]=f2tf(f.x); d[1]=f2tf(f.y); d[2]=f2tf(f.z); d[3]=f2tf(f.w);
            f = Vg4[idx];
            d = &Vs[r*VS_STRIDE + c4*4];
            d[0]=f2tf(f.x); d[1]=f2tf(f.y); d[2]=f2tf(f.z); d[3]=f2tf(f.w);
        }
        __syncthreads();

        // S = Q K^T  (warp tile 16x64)
        float s[8][4];
        #pragma unroll
        for (int ni = 0; ni < 8; ni++)
            #pragma unroll
            for (int j = 0; j < 4; j++) s[ni][j] = 0.f;

        #pragma unroll
        for (int kk = 0; kk < 16; kk++) {
            uint32_t a[4];
            a[0] = Qs[qrow    *QS_STRIDE + kk*8 + t];
            a[1] = Qs[(qrow+8)*QS_STRIDE + kk*8 + t];
            a[2] = Qs[qrow    *QS_STRIDE + kk*8 + t + 4];
            a[3] = Qs[(qrow+8)*QS_STRIDE + kk*8 + t + 4];
            #pragma unroll
            for (int ni = 0; ni < 8; ni++) {
                uint32_t bf[2];
                int kr = ni*8 + g;
                bf[0] = Ks[kr*KS_STRIDE + kk*8 + t];
                bf[1] = Ks[kr*KS_STRIDE + kk*8 + t + 4];
                mma_m16n8k8(s[ni], a, bf);
            }
        }

        // scale
        #pragma unroll
        for (int ni = 0; ni < 8; ni++)
            #pragma unroll
            for (int j = 0; j < 4; j++) s[ni][j] *= sl;

        // causal mask (only the last two K-tiles can cross the diagonal)
        if (kt >= 2*qt) {
            int q0 = qt*128 + qrow;
            #pragma unroll
            for (int ni = 0; ni < 8; ni++) {
                int kg = kt*64 + ni*8 + 2*t;
                if (kg     > q0)     s[ni][0] = NEGINF;
                if (kg + 1 > q0)     s[ni][1] = NEGINF;
                if (kg     > q0 + 8) s[ni][2] = NEGINF;
                if (kg + 1 > q0 + 8) s[ni][3] = NEGINF;
            }
        }

        // online softmax: row max
        float mx0 = NEGINF, mx1 = NEGINF;
        #pragma unroll
        for (int ni = 0; ni < 8; ni++) {
            mx0 = fmaxf(mx0, fmaxf(s[ni][0], s[ni][1]));
            mx1 = fmaxf(mx1, fmaxf(s[ni][2], s[ni][3]));
        }
        mx0 = fmaxf(mx0, __shfl_xor_sync(0xffffffffu, mx0, 1));
        mx0 = fmaxf(mx0, __shfl_xor_sync(0xffffffffu, mx0, 2));
        mx1 = fmaxf(mx1, __shfl_xor_sync(0xffffffffu, mx1, 1));
        mx1 = fmaxf(mx1, __shfl_xor_sync(0xffffffffu, mx1, 2));

        float mn0 = fmaxf(mrow0, mx0), mn1 = fmaxf(mrow1, mx1);
        float al0 = exp2f(mrow0 - mn0), al1 = exp2f(mrow1 - mn1);
        mrow0 = mn0; mrow1 = mn1;

        float rs0 = 0.f, rs1 = 0.f;
        #pragma unroll
        for (int ni = 0; ni < 8; ni++) {
            s[ni][0] = exp2f(s[ni][0] - mn0); rs0 += s[ni][0];
            s[ni][1] = exp2f(s[ni][1] - mn0); rs0 += s[ni][1];
            s[ni][2] = exp2f(s[ni][2] - mn1); rs1 += s[ni][2];
            s[ni][3] = exp2f(s[ni][3] - mn1); rs1 += s[ni][3];
        }
        rs0 += __shfl_xor_sync(0xffffffffu, rs0, 1);
        rs0 += __shfl_xor_sync(0xffffffffu, rs0, 2);
        rs1 += __shfl_xor_sync(0xffffffffu, rs1, 1);
        rs1 += __shfl_xor_sync(0xffffffffu, rs1, 2);
        lrow0 = lrow0*al0 + rs0;
        lrow1 = lrow1*al1 + rs1;

        // rescale accumulators
        #pragma unroll
        for (int ni = 0; ni < 16; ni++) {
            o[ni][0] *= al0; o[ni][1] *= al0;
            o[ni][2] *= al1; o[ni][3] *= al1;
        }

        // write P (tf32) to smem; same-warp consumer only
        #pragma unroll
        for (int ni = 0; ni < 8; ni++) {
            int col = ni*8 + 2*t;
            Ps[qrow    *PS_STRIDE + col    ] = f2tf(s[ni][0]);
            Ps[qrow    *PS_STRIDE + col + 1] = f2tf(s[ni][1]);
            Ps[(qrow+8)*PS_STRIDE + col    ] = f2tf(s[ni][2]);
            Ps[(qrow+8)*PS_STRIDE + col + 1] = f2tf(s[ni][3]);
        }
        __syncwarp();

        // O += P V
        #pragma unroll
        for (int kc = 0; kc < 8; kc++) {
            uint32_t a[4];
            a[0] = Ps[qrow    *PS_STRIDE + kc*8 + t];
            a[1] = Ps[(qrow+8)*PS_STRIDE + kc*8 + t];
            a[2] = Ps[qrow    *PS_STRIDE + kc*8 + t + 4];
            a[3] = Ps[(qrow+8)*PS_STRIDE + kc*8 + t + 4];
            #pragma unroll
            for (int ni = 0; ni < 16; ni++) {
                uint32_t bf[2];
                bf[0] = Vs[(kc*8 + t    )*VS_STRIDE + ni*8 + g];
                bf[1] = Vs[(kc*8 + t + 4)*VS_STRIDE + ni*8 + g];
                mma_m16n8k8(o[ni], a, bf);
            }
        }
        __syncthreads();
    }

    // normalize + store O in [b, s, h*HD + d] layout
    float i0 = 1.f / lrow0, i1 = 1.f / lrow1;
    int qg = qt*128 + qrow;
    float* Og = g_o + ((size_t)(b*SS + qg)) * HH + h*HD;
    #pragma unroll
    for (int ni = 0; ni < 16; ni++) {
        int d = ni*8 + 2*t;
        *reinterpret_cast<float2*>(&Og[d])            = make_float2(o[ni][0]*i0, o[ni][1]*i0);
        *reinterpret_cast<float2*>(&Og[8ull*HH + d])  = make_float2(o[ni][2]*i1, o[ni][3]*i1);
    }
}

// ============================================================================
extern "C" void kernel_launch(void* const* d_in, const int* in_sizes, int n_in,
                              void* d_out, int out_size) {
    const float* x  = (const float*)d_in[0];
    const float* wq = (const float*)d_in[1];
    const float* wk = (const float*)d_in[2];
    const float* wv = (const float*)d_in[3];
    const float* wo = (const float*)d_in[4];
    float* out = (float*)d_out;

    float *q, *k, *v, *o;
    cudaGetSymbolAddress((void**)&q, g_q);
    cudaGetSymbolAddress((void**)&k, g_k);
    cudaGetSymbolAddress((void**)&v, g_v);
    cudaGetSymbolAddress((void**)&o, g_o);

    cudaFuncSetAttribute(attn_kernel, cudaFuncAttributeMaxDynamicSharedMemorySize, ATTN_SMEM);

    dim3 gblk(256);
    dim3 ggrd(HH/128, MM/128);   // (16, 64)

    gemm_tf32_kernel<<<ggrd, gblk>>>(x, wq, q, 1);
    gemm_tf32_kernel<<<ggrd, gblk>>>(x, wk, k, 1);
    gemm_tf32_kernel<<<ggrd, gblk>>>(x, wv, v, 1);

    attn_kernel<<<dim3(SS/128, NH, BB), 256, ATTN_SMEM>>>();

    gemm_tf32_kernel<<<ggrd, gblk>>>(o, wo, out, 0);
}

// round 6
// speedup vs baseline: 1.2725x; 1.2725x over previous
#include <cuda_runtime.h>
#include <cstdint>

// Problem constants
#define BB 4
#define SS 2048
#define HH 2048
#define NH 16
#define HD 128
#define MM (BB*SS)            // 8192 rows

// Scratch (allocation-free: __device__ globals)
__device__ float g_q[BB*NH*SS*HD];   // [b,h,s,d]  (tf32-rounded)
__device__ float g_k[BB*NH*SS*HD];
__device__ float g_v[BB*NH*SS*HD];
__device__ float g_o[MM*HH];         // [b,s,h*d]  (tf32-rounded)
__device__ float g_x[MM*HH];         // tf32-rounded x
__device__ float g_w[4][HH*HH];      // tf32-rounded weights (q,k,v,o)

__device__ __forceinline__ uint32_t f2tf(float f) {
    uint32_t u; asm("cvt.rna.tf32.f32 %0, %1;" : "=r"(u) : "f"(f)); return u;
}

__device__ __forceinline__ void mma_m16n8k8(float c[4], const uint32_t a[4], const uint32_t b[2]) {
    asm volatile(
        "mma.sync.aligned.m16n8k8.row.col.f32.tf32.tf32.f32 "
        "{%0,%1,%2,%3},{%4,%5,%6,%7},{%8,%9},{%0,%1,%2,%3};"
        : "+f"(c[0]), "+f"(c[1]), "+f"(c[2]), "+f"(c[3])
        : "r"(a[0]), "r"(a[1]), "r"(a[2]), "r"(a[3]), "r"(b[0]), "r"(b[1]));
}

__device__ __forceinline__ void cpa16(uint32_t s, const float* g) {
    asm volatile("cp.async.cg.shared.global [%0], [%1], 16;\n" :: "r"(s), "l"(g));
}
__device__ __forceinline__ void cpa_commit() {
    asm volatile("cp.async.commit_group;\n" ::: "memory");
}
template<int N> __device__ __forceinline__ void cpa_wait() {
    asm volatile("cp.async.wait_group %0;\n" :: "n"(N) : "memory");
}

// ============================================================================
// Elementwise tf32 rounding pass
// ============================================================================
__global__ void round_tf32_kernel(const float* __restrict__ in, float* __restrict__ out, int n4) {
    int i = blockIdx.x * blockDim.x + threadIdx.x;
    if (i < n4) {
        float4 f = reinterpret_cast<const float4*>(in)[i];
        uint4 u;
        u.x = f2tf(f.x); u.y = f2tf(f.y); u.z = f2tf(f.z); u.w = f2tf(f.w);
        reinterpret_cast<uint4*>(out)[i] = u;
    }
}

// ============================================================================
// GEMM: C[M,N] = A[M,K] * Bw[N,K]^T   (tf32 mma, 128x128x32 tiles, 3-stage
// cp.async pipeline, 256 thr). Inputs pre-rounded to tf32.
// qkv_mode=1: scatter + tf32-round C -> out[b,h,s,d] layout
// ============================================================================
#define GBK 32
#define GSTG 3
#define GAS 36    // smem row stride (floats): 36 mod 32 = 4 -> conflict-free frags
#define GEMM_SMEM (GSTG * 2 * 128 * GAS * 4)   // 110592 bytes

__global__ void __launch_bounds__(256) gemm_tf32_kernel(
    const float* __restrict__ A, const float* __restrict__ Bw,
    float* __restrict__ C, int qkv_mode)
{
    const int K = HH, N = HH;
    extern __shared__ float sm[];
    float* As = sm;                         // [GSTG][128][GAS]
    float* Bs = sm + GSTG * 128 * GAS;

    const int tid  = threadIdx.x;
    const int lane = tid & 31;
    const int warp = tid >> 5;
    const int g = lane >> 2, t = lane & 3;
    const int wm = warp & 3, wn = warp >> 2;     // 4 x 2 warp grid, warp tile 32x64
    const int rowBase = blockIdx.y * 128;
    const int colBase = blockIdx.x * 128;

    const int lr = tid >> 3;        // 0..31
    const int lc = (tid & 7) * 4;   // 0,4,..,28

    const uint32_t sA = (uint32_t)__cvta_generic_to_shared(As);
    const uint32_t sB = (uint32_t)__cvta_generic_to_shared(Bs);

    const float* gA = A  + (size_t)rowBase * K;
    const float* gB = Bw + (size_t)colBase * K;

    auto load_stage = [&](int s, int kt) {
        uint32_t bA = sA + (uint32_t)(s * 128 * GAS) * 4u;
        uint32_t bB = sB + (uint32_t)(s * 128 * GAS) * 4u;
        const float* pA = gA + kt * GBK;
        const float* pB = gB + kt * GBK;
        #pragma unroll
        for (int i = 0; i < 4; i++) {
            int r = lr + i * 32;
            cpa16(bA + (uint32_t)(r * GAS + lc) * 4u, pA + (size_t)r * K + lc);
            cpa16(bB + (uint32_t)(r * GAS + lc) * 4u, pB + (size_t)r * K + lc);
        }
        cpa_commit();
    };

    float acc[2][8][4];
    #pragma unroll
    for (int mi = 0; mi < 2; mi++)
        #pragma unroll
        for (int ni = 0; ni < 8; ni++)
            #pragma unroll
            for (int j = 0; j < 4; j++) acc[mi][ni][j] = 0.f;

    load_stage(0, 0);
    load_stage(1, 1);
    cpa_wait<1>();
    __syncthreads();

    const int nk = K / GBK;   // 64
    #pragma unroll 1
    for (int kt = 0; kt < nk; kt++) {
        const int cur = kt % GSTG;
        if (kt + 2 < nk) load_stage((kt + 2) % GSTG, kt + 2);
        else             cpa_commit();

        const float* Ac = As + cur * 128 * GAS;
        const float* Bc = Bs + cur * 128 * GAS;

        #pragma unroll
        for (int kk = 0; kk < 4; kk++) {
            uint32_t a[2][4];
            #pragma unroll
            for (int mi = 0; mi < 2; mi++) {
                int r = wm * 32 + mi * 16 + g;
                a[mi][0] = __float_as_uint(Ac[r * GAS + kk * 8 + t]);
                a[mi][1] = __float_as_uint(Ac[(r + 8) * GAS + kk * 8 + t]);
                a[mi][2] = __float_as_uint(Ac[r * GAS + kk * 8 + t + 4]);
                a[mi][3] = __float_as_uint(Ac[(r + 8) * GAS + kk * 8 + t + 4]);
            }
            #pragma unroll
            for (int ni = 0; ni < 8; ni++) {
                uint32_t bf[2];
                int bn = wn * 64 + ni * 8 + g;
                bf[0] = __float_as_uint(Bc[bn * GAS + kk * 8 + t]);
                bf[1] = __float_as_uint(Bc[bn * GAS + kk * 8 + t + 4]);
                mma_m16n8k8(acc[0][ni], a[0], bf);
                mma_m16n8k8(acc[1][ni], a[1], bf);
            }
        }
        cpa_wait<1>();
        __syncthreads();
    }

    // epilogue
    #pragma unroll
    for (int mi = 0; mi < 2; mi++) {
        int r0 = rowBase + wm * 32 + mi * 16 + g;
        #pragma unroll
        for (int ni = 0; ni < 8; ni++) {
            int cc = colBase + wn * 64 + ni * 8 + 2 * t;
            if (!qkv_mode) {
                float* dst = C + (size_t)r0 * N + cc;
                *reinterpret_cast<float2*>(dst)           = make_float2(acc[mi][ni][0], acc[mi][ni][1]);
                *reinterpret_cast<float2*>(dst + 8ull*N)  = make_float2(acc[mi][ni][2], acc[mi][ni][3]);
            } else {
                int bb2 = r0 >> 11;
                int ss2 = r0 & 2047;
                int hh2 = cc >> 7;
                int dd  = cc & 127;
                float* dst = C + (((size_t)(bb2 * NH + hh2)) << 18) + (size_t)ss2 * HD + dd;
                float2 v0 = make_float2(__uint_as_float(f2tf(acc[mi][ni][0])),
                                        __uint_as_float(f2tf(acc[mi][ni][1])));
                float2 v1 = make_float2(__uint_as_float(f2tf(acc[mi][ni][2])),
                                        __uint_as_float(f2tf(acc[mi][ni][3])));
                *reinterpret_cast<float2*>(dst)          = v0;
                *reinterpret_cast<float2*>(dst + 8 * HD) = v1;
            }
        }
    }
}

// ============================================================================
// Flash attention (causal), tf32 mma. Q tile 128, K/V tile 64, 256 threads.
// Q cp.async once; K double-buffered cp.async; V single-buffer cp.async
// overlapped with S-compute + softmax. Inputs pre-rounded to tf32.
// ============================================================================
#define QS_STRIDE 132   //  4 mod 32
#define KS_STRIDE 132
#define VS_STRIDE 136   //  8 mod 32
#define PS_STRIDE 68    //  4 mod 32

#define ATTN_SMEM ((128*QS_STRIDE + 2*64*KS_STRIDE + 64*VS_STRIDE + 128*PS_STRIDE) * 4)

__global__ void __launch_bounds__(256) attn_kernel()
{
    extern __shared__ float smf[];
    float* Qs = smf;                             // [128][QS_STRIDE]
    float* Ks = Qs + 128 * QS_STRIDE;            // [2][64][KS_STRIDE]
    float* Vs = Ks + 2 * 64 * KS_STRIDE;         // [64][VS_STRIDE]
    float* Ps = Vs + 64 * VS_STRIDE;             // [128][PS_STRIDE]

    const int tid  = threadIdx.x;
    const int lane = tid & 31;
    const int warp = tid >> 5;
    const int g = lane >> 2, t = lane & 3;

    const int qt = blockIdx.x;
    const int h  = blockIdx.y;
    const int b  = blockIdx.z;

    const size_t base = ((size_t)(b * NH + h)) << 18;   // * S*HD
    const float* Qg = g_q + base + (size_t)qt * 128 * HD;
    const float* Kg = g_k + base;
    const float* Vg = g_v + base;

    const uint32_t sQ = (uint32_t)__cvta_generic_to_shared(Qs);
    const uint32_t sK = (uint32_t)__cvta_generic_to_shared(Ks);
    const uint32_t sV = (uint32_t)__cvta_generic_to_shared(Vs);

    const int lr = tid >> 3;        // 0..31
    const int lc = (tid & 7) * 4;   // 0..28

    // Q: 128 x 128 floats = 4096 float4; 16 chunks per thread  (group 1)
    #pragma unroll
    for (int i = 0; i < 4; i++) {
        int r = lr + i * 32;
        #pragma unroll
        for (int j = 0; j < 4; j++)
            cpa16(sQ + (uint32_t)(r * QS_STRIDE + j * 32 + lc) * 4u,
                  Qg + (size_t)r * HD + j * 32 + lc);
    }
    cpa_commit();

    // K tile 0 -> stage 0  (group 2)
    #pragma unroll
    for (int i = 0; i < 2; i++) {
        int r = lr + i * 32;
        #pragma unroll
        for (int j = 0; j < 4; j++)
            cpa16(sK + (uint32_t)(r * KS_STRIDE + j * 32 + lc) * 4u,
                  Kg + (size_t)r * HD + j * 32 + lc);
    }
    cpa_commit();

    float o[16][4];
    #pragma unroll
    for (int ni = 0; ni < 16; ni++)
        #pragma unroll
        for (int j = 0; j < 4; j++) o[ni][j] = 0.f;

    const float NEGINF = -1e30f;
    float mrow0 = NEGINF, mrow1 = NEGINF;
    float lrow0 = 0.f,    lrow1 = 0.f;
    const float sl = 0.088388347648318447f * 1.4426950408889634f;  // 1/sqrt(128)*log2(e)

    const int qrow = warp * 16 + g;
    const int nkt = 2 * qt + 2;

    #pragma unroll 1
    for (int kt = 0; kt < nkt; kt++) {
        const int cur = kt & 1, nxt = cur ^ 1;

        // issue V[kt] -> Vs (single buffer; prev PV done, protected by trailing sync)
        {
            const float* Vg4 = Vg + (size_t)kt * 64 * HD;
            #pragma unroll
            for (int i = 0; i < 2; i++) {
                int r = lr + i * 32;
                #pragma unroll
                for (int j = 0; j < 4; j++)
                    cpa16(sV + (uint32_t)(r * VS_STRIDE + j * 32 + lc) * 4u,
                          Vg4 + (size_t)r * HD + j * 32 + lc);
            }
            cpa_commit();
        }
        // issue K[kt+1] -> stage nxt
        if (kt + 1 < nkt) {
            const float* Kg4 = Kg + (size_t)(kt + 1) * 64 * HD;
            uint32_t bK = sK + (uint32_t)(nxt * 64 * KS_STRIDE) * 4u;
            #pragma unroll
            for (int i = 0; i < 2; i++) {
                int r = lr + i * 32;
                #pragma unroll
                for (int j = 0; j < 4; j++)
                    cpa16(bK + (uint32_t)(r * KS_STRIDE + j * 32 + lc) * 4u,
                          Kg4 + (size_t)r * HD + j * 32 + lc);
            }
        }
        cpa_commit();   // always commit (possibly empty) to keep group counting fixed

        // wait: everything older than {V[kt], K[kt+1]} done  => Q + K[cur] ready
        cpa_wait<2>();
        __syncthreads();

        const float* Kc = Ks + cur * 64 * KS_STRIDE;

        // S = Q K^T  (warp tile 16x64)
        float s[8][4];
        #pragma unroll
        for (int ni = 0; ni < 8; ni++)
            #pragma unroll
            for (int j = 0; j < 4; j++) s[ni][j] = 0.f;

        #pragma unroll
        for (int kk = 0; kk < 16; kk++) {
            uint32_t a[4];
            a[0] = __float_as_uint(Qs[qrow       * QS_STRIDE + kk * 8 + t]);
            a[1] = __float_as_uint(Qs[(qrow + 8) * QS_STRIDE + kk * 8 + t]);
            a[2] = __float_as_uint(Qs[qrow       * QS_STRIDE + kk * 8 + t + 4]);
            a[3] = __float_as_uint(Qs[(qrow + 8) * QS_STRIDE + kk * 8 + t + 4]);
            #pragma unroll
            for (int ni = 0; ni < 8; ni++) {
                uint32_t bf[2];
                int kr = ni * 8 + g;
                bf[0] = __float_as_uint(Kc[kr * KS_STRIDE + kk * 8 + t]);
                bf[1] = __float_as_uint(Kc[kr * KS_STRIDE + kk * 8 + t + 4]);
                mma_m16n8k8(s[ni], a, bf);
            }
        }

        #pragma unroll
        for (int ni = 0; ni < 8; ni++)
            #pragma unroll
            for (int j = 0; j < 4; j++) s[ni][j] *= sl;

        // causal mask
        if (kt >= 2 * qt) {
            int q0 = qt * 128 + qrow;
            #pragma unroll
            for (int ni = 0; ni < 8; ni++) {
                int kg = kt * 64 + ni * 8 + 2 * t;
                if (kg     > q0)     s[ni][0] = NEGINF;
                if (kg + 1 > q0)     s[ni][1] = NEGINF;
                if (kg     > q0 + 8) s[ni][2] = NEGINF;
                if (kg + 1 > q0 + 8) s[ni][3] = NEGINF;
            }
        }

        // online softmax
        float mx0 = NEGINF, mx1 = NEGINF;
        #pragma unroll
        for (int ni = 0; ni < 8; ni++) {
            mx0 = fmaxf(mx0, fmaxf(s[ni][0], s[ni][1]));
            mx1 = fmaxf(mx1, fmaxf(s[ni][2], s[ni][3]));
        }
        mx0 = fmaxf(mx0, __shfl_xor_sync(0xffffffffu, mx0, 1));
        mx0 = fmaxf(mx0, __shfl_xor_sync(0xffffffffu, mx0, 2));
        mx1 = fmaxf(mx1, __shfl_xor_sync(0xffffffffu, mx1, 1));
        mx1 = fmaxf(mx1, __shfl_xor_sync(0xffffffffu, mx1, 2));

        float mn0 = fmaxf(mrow0, mx0), mn1 = fmaxf(mrow1, mx1);
        float al0 = exp2f(mrow0 - mn0), al1 = exp2f(mrow1 - mn1);
        mrow0 = mn0; mrow1 = mn1;

        float rs0 = 0.f, rs1 = 0.f;
        #pragma unroll
        for (int ni = 0; ni < 8; ni++) {
            s[ni][0] = exp2f(s[ni][0] - mn0); rs0 += s[ni][0];
            s[ni][1] = exp2f(s[ni][1] - mn0); rs0 += s[ni][1];
            s[ni][2] = exp2f(s[ni][2] - mn1); rs1 += s[ni][2];
            s[ni][3] = exp2f(s[ni][3] - mn1); rs1 += s[ni][3];
        }
        rs0 += __shfl_xor_sync(0xffffffffu, rs0, 1);
        rs0 += __shfl_xor_sync(0xffffffffu, rs0, 2);
        rs1 += __shfl_xor_sync(0xffffffffu, rs1, 1);
        rs1 += __shfl_xor_sync(0xffffffffu, rs1, 2);
        lrow0 = lrow0 * al0 + rs0;
        lrow1 = lrow1 * al1 + rs1;

        #pragma unroll
        for (int ni = 0; ni < 16; ni++) {
            o[ni][0] *= al0; o[ni][1] *= al0;
            o[ni][2] *= al1; o[ni][3] *= al1;
        }

        // write P (tf32) to smem; same-warp consumer only
        #pragma unroll
        for (int ni = 0; ni < 8; ni++) {
            int col = ni * 8 + 2 * t;
            Ps[qrow       * PS_STRIDE + col    ] = __uint_as_float(f2tf(s[ni][0]));
            Ps[qrow       * PS_STRIDE + col + 1] = __uint_as_float(f2tf(s[ni][1]));
            Ps[(qrow + 8) * PS_STRIDE + col    ] = __uint_as_float(f2tf(s[ni][2]));
            Ps[(qrow + 8) * PS_STRIDE + col + 1] = __uint_as_float(f2tf(s[ni][3]));
        }
        __syncwarp();

        // V[kt] must be complete in every thread before PV
        cpa_wait<1>();
        __syncthreads();

        // O += P V
        #pragma unroll
        for (int kc = 0; kc < 8; kc++) {
            uint32_t a[4];
            a[0] = __float_as_uint(Ps[qrow       * PS_STRIDE + kc * 8 + t]);
            a[1] = __float_as_uint(Ps[(qrow + 8) * PS_STRIDE + kc * 8 + t]);
            a[2] = __float_as_uint(Ps[qrow       * PS_STRIDE + kc * 8 + t + 4]);
            a[3] = __float_as_uint(Ps[(qrow + 8) * PS_STRIDE + kc * 8 + t + 4]);
            #pragma unroll
            for (int ni = 0; ni < 16; ni++) {
                uint32_t bf[2];
                bf[0] = __float_as_uint(Vs[(kc * 8 + t    ) * VS_STRIDE + ni * 8 + g]);
                bf[1] = __float_as_uint(Vs[(kc * 8 + t + 4) * VS_STRIDE + ni * 8 + g]);
                mma_m16n8k8(o[ni], a, bf);
            }
        }
        __syncthreads();   // protect Vs + K[cur] before next iteration's cp.asyncs
    }

    // normalize + tf32-round + store O in [b, s, h*HD + d] layout
    float i0 = 1.f / lrow0, i1 = 1.f / lrow1;
    int qg = qt * 128 + qrow;
    float* Og = g_o + ((size_t)(b * SS + qg)) * HH + h * HD;
    #pragma unroll
    for (int ni = 0; ni < 16; ni++) {
        int d = ni * 8 + 2 * t;
        float2 v0 = make_float2(__uint_as_float(f2tf(o[ni][0] * i0)),
                                __uint_as_float(f2tf(o[ni][1] * i0)));
        float2 v1 = make_float2(__uint_as_float(f2tf(o[ni][2] * i1)),
                                __uint_as_float(f2tf(o[ni][3] * i1)));
        *reinterpret_cast<float2*>(&Og[d])           = v0;
        *reinterpret_cast<float2*>(&Og[8ull * HH + d]) = v1;
    }
}

// ============================================================================
extern "C" void kernel_launch(void* const* d_in, const int* in_sizes, int n_in,
                              void* d_out, int out_size) {
    const float* x  = (const float*)d_in[0];
    const float* wq = (const float*)d_in[1];
    const float* wk = (const float*)d_in[2];
    const float* wv = (const float*)d_in[3];
    const float* wo = (const float*)d_in[4];
    float* out = (float*)d_out;

    float *q, *k, *v, *o, *xr, *wr;
    cudaGetSymbolAddress((void**)&q,  g_q);
    cudaGetSymbolAddress((void**)&k,  g_k);
    cudaGetSymbolAddress((void**)&v,  g_v);
    cudaGetSymbolAddress((void**)&o,  g_o);
    cudaGetSymbolAddress((void**)&xr, g_x);
    cudaGetSymbolAddress((void**)&wr, g_w);

    cudaFuncSetAttribute(gemm_tf32_kernel, cudaFuncAttributeMaxDynamicSharedMemorySize, GEMM_SMEM);
    cudaFuncSetAttribute(attn_kernel,      cudaFuncAttributeMaxDynamicSharedMemorySize, ATTN_SMEM);

    // pre-round inputs to tf32
    const int XN4 = MM * HH / 4;       // 4,194,304
    const int WN4 = HH * HH / 4;       // 1,048,576
    round_tf32_kernel<<<(XN4 + 255) / 256, 256>>>(x,  xr, XN4);
    round_tf32_kernel<<<(WN4 + 255) / 256, 256>>>(wq, wr + 0ull * HH * HH, WN4);
    round_tf32_kernel<<<(WN4 + 255) / 256, 256>>>(wk, wr + 1ull * HH * HH, WN4);
    round_tf32_kernel<<<(WN4 + 255) / 256, 256>>>(wv, wr + 2ull * HH * HH, WN4);
    round_tf32_kernel<<<(WN4 + 255) / 256, 256>>>(wo, wr + 3ull * HH * HH, WN4);

    dim3 gblk(256);
    dim3 ggrd(HH / 128, MM / 128);   // (16, 64)

    gemm_tf32_kernel<<<ggrd, gblk, GEMM_SMEM>>>(xr, wr + 0ull * HH * HH, q, 1);
    gemm_tf32_kernel<<<ggrd, gblk, GEMM_SMEM>>>(xr, wr + 1ull * HH * HH, k, 1);
    gemm_tf32_kernel<<<ggrd, gblk, GEMM_SMEM>>>(xr, wr + 2ull * HH * HH, v, 1);

    attn_kernel<<<dim3(SS / 128, NH, BB), 256, ATTN_SMEM>>>();

    gemm_tf32_kernel<<<ggrd, gblk, GEMM_SMEM>>>(o, wr + 3ull * HH * HH, out, 0);
}